// round 1
// baseline (speedup 1.0000x reference)
#include <cuda_runtime.h>

// Problem constants (fixed by the reference)
constexpr int KC = 5;      // kernel size
constexpr int PC = 2;      // pad = K/2
constexpr int BC = 2;
constexpr int NC = 8;
constexpr int HC = 512;
constexpr int WC = 512;

// Tile config
constexpr int TH = 16;     // tile height (output rows per CTA)
constexpr int TW = 128;    // tile width  (output cols per CTA)
constexpr int SH = TH + 2 * PC;  // 20
constexpr int SW = TW + 2 * PC;  // 132 floats -> 528B row pitch (16B aligned)

__global__ __launch_bounds__(256, 4)
void kconv_kernel(const float* __restrict__ frames,
                  const float* __restrict__ core,
                  const float* __restrict__ Wt,
                  float* __restrict__ out)
{
    __shared__ float s[SH][SW];

    const int tx = blockIdx.x * TW;          // tile origin x
    const int ty = blockIdx.y * TH;          // tile origin y
    const int bz = blockIdx.z;               // b*N + n
    const int b  = bz >> 3;                  // / NC
    const int n  = bz & 7;                   // % NC

    const size_t plane = (size_t)HC * WC;
    const float* fbase = frames + (size_t)bz * plane;

    // ---- Stage padded frame tile into shared memory (zero halo at borders) ----
    for (int idx = threadIdx.x; idx < SH * SW; idx += 256) {
        const int r = idx / SW;
        const int c = idx - r * SW;
        const int gy = ty + r - PC;
        const int gx = tx + c - PC;
        float v = 0.0f;
        if ((unsigned)gy < (unsigned)HC && (unsigned)gx < (unsigned)WC)
            v = fbase[(size_t)gy * WC + gx];
        s[r][c] = v;
    }
    __syncthreads();

    // core channel base for (b, n): layout [B, N*K*K, H, W], channel = n*25 + k
    const float* cbase = core + ((size_t)(b * NC + n) * (KC * KC)) * plane;
    const float* wbase = Wt  + (size_t)bz * plane;
    float*       obase = out + (size_t)bz * plane;

    // ---- Each thread computes 2 groups of 4 consecutive output pixels ----
    #pragma unroll
    for (int pass = 0; pass < 2; ++pass) {
        const int g   = threadIdx.x + pass * 256;  // 0..511 groups (16 rows * 32 groups)
        const int row = g >> 5;                    // 0..15 within tile
        const int xx  = (g & 31) << 2;             // 0..124, multiple of 4
        const int gy  = ty + row;
        const int gx  = tx + xx;
        const size_t pix = (size_t)gy * WC + gx;

        float acc0 = 0.f, acc1 = 0.f, acc2 = 0.f, acc3 = 0.f;

        #pragma unroll
        for (int i = 0; i < KC; ++i) {
            // 8-float sliding window from shared (two aligned 16B loads)
            const float* srow = &s[row + i][xx];
            const float4 a = *reinterpret_cast<const float4*>(srow);
            const float4 bq = *reinterpret_cast<const float4*>(srow + 4);
            const float w[8] = { a.x, a.y, a.z, a.w, bq.x, bq.y, bq.z, bq.w };

            #pragma unroll
            for (int j = 0; j < KC; ++j) {
                const int k = i * KC + j;
                const float4 cv =
                    *reinterpret_cast<const float4*>(cbase + (size_t)k * plane + pix);
                acc0 = fmaf(cv.x, w[j + 0], acc0);
                acc1 = fmaf(cv.y, w[j + 1], acc1);
                acc2 = fmaf(cv.z, w[j + 2], acc2);
                acc3 = fmaf(cv.w, w[j + 3], acc3);
            }
        }

        const float4 wv = *reinterpret_cast<const float4*>(wbase + pix);
        float4 o;
        o.x = acc0 * wv.x;
        o.y = acc1 * wv.y;
        o.z = acc2 * wv.z;
        o.w = acc3 * wv.w;
        *reinterpret_cast<float4*>(obase + pix) = o;
    }
}

extern "C" void kernel_launch(void* const* d_in, const int* in_sizes, int n_in,
                              void* d_out, int out_size)
{
    const float* frames = (const float*)d_in[0];
    const float* core   = (const float*)d_in[1];
    const float* Wt     = (const float*)d_in[2];
    float* out          = (float*)d_out;

    dim3 grid(WC / TW, HC / TH, BC * NC);   // (4, 32, 16) = 2048 CTAs
    dim3 block(256);
    kconv_kernel<<<grid, block>>>(frames, core, Wt, out);
}

// round 2
// speedup vs baseline: 1.1769x; 1.1769x over previous
#include <cuda_runtime.h>

// Problem constants (fixed by the reference)
constexpr int KC = 5;      // kernel size
constexpr int PC = 2;      // pad = K/2
constexpr int BC = 2;
constexpr int NC = 8;
constexpr int HC = 512;
constexpr int WC = 512;

// Tile config
constexpr int TH = 16;     // tile height (output rows per CTA)
constexpr int TW = 128;    // tile width  (output cols per CTA)
constexpr int SH = TH + 2 * PC;  // 20
constexpr int SW = TW + 2 * PC;  // 132 floats -> 528B row pitch (16B aligned)

__global__ __launch_bounds__(256, 4)
void kconv_kernel(const float* __restrict__ frames,
                  const float* __restrict__ core,
                  const float* __restrict__ Wt,
                  float* __restrict__ out)
{
    __shared__ float s[SH][SW];

    const int tx = blockIdx.x * TW;          // tile origin x
    const int ty = blockIdx.y * TH;          // tile origin y
    const int bz = blockIdx.z;               // b*N + n

    const size_t plane = (size_t)HC * WC;
    const float* fbase = frames + (size_t)bz * plane;

    // ---- Stage padded frame tile into shared memory (zero halo at borders) ----
    for (int idx = threadIdx.x; idx < SH * SW; idx += 256) {
        const int r = idx / SW;
        const int c = idx - r * SW;
        const int gy = ty + r - PC;
        const int gx = tx + c - PC;
        float v = 0.0f;
        if ((unsigned)gy < (unsigned)HC && (unsigned)gx < (unsigned)WC)
            v = __ldg(&fbase[(size_t)gy * WC + gx]);
        s[r][c] = v;
    }
    __syncthreads();

    // core channel base for (b, n): layout [B, N*K*K, H, W], channel = n*25 + k
    const float* cbase = core + (size_t)bz * (KC * KC) * plane;
    const float* wbase = Wt  + (size_t)bz * plane;
    float*       obase = out + (size_t)bz * plane;

    // ---- Each thread computes 2 groups of 4 consecutive output pixels ----
    #pragma unroll
    for (int pass = 0; pass < 2; ++pass) {
        const int g   = threadIdx.x + pass * 256;  // 0..511 groups (16 rows * 32 groups)
        const int row = g >> 5;                    // 0..15 within tile
        const int xx  = (g & 31) << 2;             // 0..124, multiple of 4
        const int gy  = ty + row;
        const int gx  = tx + xx;
        const size_t pix = (size_t)gy * WC + gx;

        // Preload the full 5x8 frame window from shared memory FIRST, so the
        // hot loop below is a pure LDG->FMA stream (deep pipelining, no LDS
        // interleaved with the global-load burst).
        float w[KC][8];
        #pragma unroll
        for (int i = 0; i < KC; ++i) {
            const float* srow = &s[row + i][xx];
            const float4 a  = *reinterpret_cast<const float4*>(srow);
            const float4 bq = *reinterpret_cast<const float4*>(srow + 4);
            w[i][0] = a.x;  w[i][1] = a.y;  w[i][2] = a.z;  w[i][3] = a.w;
            w[i][4] = bq.x; w[i][5] = bq.y; w[i][6] = bq.z; w[i][7] = bq.w;
        }

        float acc0 = 0.f, acc1 = 0.f, acc2 = 0.f, acc3 = 0.f;

        #pragma unroll
        for (int i = 0; i < KC; ++i) {
            #pragma unroll
            for (int j = 0; j < KC; ++j) {
                const int k = i * KC + j;
                // evict-first: core is a 419MB read-once stream, keep it out
                // of L2's way (frames/W halo lines have real cross-CTA reuse)
                const float4 cv = __ldcs(
                    reinterpret_cast<const float4*>(cbase + (size_t)k * plane + pix));
                acc0 = fmaf(cv.x, w[i][j + 0], acc0);
                acc1 = fmaf(cv.y, w[i][j + 1], acc1);
                acc2 = fmaf(cv.z, w[i][j + 2], acc2);
                acc3 = fmaf(cv.w, w[i][j + 3], acc3);
            }
        }

        const float4 wv = *reinterpret_cast<const float4*>(wbase + pix);
        float4 o;
        o.x = acc0 * wv.x;
        o.y = acc1 * wv.y;
        o.z = acc2 * wv.z;
        o.w = acc3 * wv.w;
        // streaming store: output is write-once, never re-read
        __stcs(reinterpret_cast<float4*>(obase + pix), o);
    }
}

extern "C" void kernel_launch(void* const* d_in, const int* in_sizes, int n_in,
                              void* d_out, int out_size)
{
    const float* frames = (const float*)d_in[0];
    const float* core   = (const float*)d_in[1];
    const float* Wt     = (const float*)d_in[2];
    float* out          = (float*)d_out;

    dim3 grid(WC / TW, HC / TH, BC * NC);   // (4, 32, 16) = 2048 CTAs
    dim3 block(256);
    kconv_kernel<<<grid, block>>>(frames, core, Wt, out);
}

// round 3
// speedup vs baseline: 1.2126x; 1.0303x over previous
#include <cuda_runtime.h>

// Problem constants (fixed by the reference)
constexpr int KC = 5;      // kernel size
constexpr int PC = 2;      // pad = K/2
constexpr int BC = 2;
constexpr int NC = 8;
constexpr int HC = 512;
constexpr int WC = 512;

// Tile config: 16 rows x 64 cols per CTA -> 4096 CTAs (smoother drain tail)
constexpr int TH = 16;
constexpr int TW = 64;
constexpr int SH = TH + 2 * PC;  // 20
constexpr int SW = TW + 2 * PC;  // 68 floats -> 272B row pitch (16B aligned)

__global__ __launch_bounds__(256, 4)
void kconv_kernel(const float* __restrict__ frames,
                  const float* __restrict__ core,
                  const float* __restrict__ Wt,
                  float* __restrict__ out)
{
    __shared__ float s[SH][SW];

    const int tx = blockIdx.x * TW;          // tile origin x
    const int ty = blockIdx.y * TH;          // tile origin y
    const int bz = blockIdx.z;               // b*N + n

    const size_t plane = (size_t)HC * WC;
    const float* fbase = frames + (size_t)bz * plane;

    // ---- Stage padded frame tile into shared memory (zero halo at borders) ----
    for (int idx = threadIdx.x; idx < SH * SW; idx += 256) {
        const int r = idx / SW;
        const int c = idx - r * SW;
        const int gy = ty + r - PC;
        const int gx = tx + c - PC;
        float v = 0.0f;
        if ((unsigned)gy < (unsigned)HC && (unsigned)gx < (unsigned)WC)
            v = __ldg(&fbase[(size_t)gy * WC + gx]);
        s[r][c] = v;
    }
    __syncthreads();

    // core channel base for (b, n): layout [B, N*K*K, H, W], channel = n*25 + k
    const float* cbase = core + (size_t)bz * (KC * KC) * plane;
    const float* wbase = Wt  + (size_t)bz * plane;
    float*       obase = out + (size_t)bz * plane;

    // ---- Each thread computes one group of 4 consecutive output pixels ----
    const int g   = threadIdx.x;             // 0..255 (16 rows * 16 groups)
    const int row = g >> 4;                  // 0..15 within tile
    const int xx  = (g & 15) << 2;           // 0..60, multiple of 4
    const int gy  = ty + row;
    const int gx  = tx + xx;
    const size_t pix = (size_t)gy * WC + gx;

    // Preload the full 5x8 frame window from shared memory FIRST, so the
    // hot loop below is a pure LDG->FMA stream (deep pipelining, no LDS
    // interleaved with the global-load burst).
    float w[KC][8];
    #pragma unroll
    for (int i = 0; i < KC; ++i) {
        const float* srow = &s[row + i][xx];
        const float4 a  = *reinterpret_cast<const float4*>(srow);
        const float4 bq = *reinterpret_cast<const float4*>(srow + 4);
        w[i][0] = a.x;  w[i][1] = a.y;  w[i][2] = a.z;  w[i][3] = a.w;
        w[i][4] = bq.x; w[i][5] = bq.y; w[i][6] = bq.z; w[i][7] = bq.w;
    }

    float acc0 = 0.f, acc1 = 0.f, acc2 = 0.f, acc3 = 0.f;

    #pragma unroll
    for (int i = 0; i < KC; ++i) {
        #pragma unroll
        for (int j = 0; j < KC; ++j) {
            const int k = i * KC + j;
            // evict-first: core is a 419MB read-once stream, keep it out
            // of L2's way (frames halo lines have real cross-CTA reuse)
            const float4 cv = __ldcs(
                reinterpret_cast<const float4*>(cbase + (size_t)k * plane + pix));
            acc0 = fmaf(cv.x, w[i][j + 0], acc0);
            acc1 = fmaf(cv.y, w[i][j + 1], acc1);
            acc2 = fmaf(cv.z, w[i][j + 2], acc2);
            acc3 = fmaf(cv.w, w[i][j + 3], acc3);
        }
    }

    // W is also a read-once stream: evict-first
    const float4 wv = __ldcs(reinterpret_cast<const float4*>(wbase + pix));
    float4 o;
    o.x = acc0 * wv.x;
    o.y = acc1 * wv.y;
    o.z = acc2 * wv.z;
    o.w = acc3 * wv.w;
    // streaming store: output is write-once, never re-read
    __stcs(reinterpret_cast<float4*>(obase + pix), o);
}

extern "C" void kernel_launch(void* const* d_in, const int* in_sizes, int n_in,
                              void* d_out, int out_size)
{
    const float* frames = (const float*)d_in[0];
    const float* core   = (const float*)d_in[1];
    const float* Wt     = (const float*)d_in[2];
    float* out          = (float*)d_out;

    dim3 grid(WC / TW, HC / TH, BC * NC);   // (8, 32, 16) = 4096 CTAs
    dim3 block(256);
    kconv_kernel<<<grid, block>>>(frames, core, Wt, out);
}

// round 4
// speedup vs baseline: 1.2131x; 1.0005x over previous
#include <cuda_runtime.h>

// Problem constants (fixed by the reference)
constexpr int KC = 5;      // kernel size
constexpr int PC = 2;      // pad = K/2
constexpr int BC = 2;
constexpr int NC = 8;
constexpr int HC = 512;
constexpr int WC = 512;

// Tile config: 32 rows x 64 cols per CTA, 512 threads.
// Same warps/SM as before (2 CTAs x 512 = 1024 thr) but HALF the CTAs per SM:
// halves the cross-CTA L1tex-queue contention term (oe * MLP_p1) that causes
// per-wave straggler spread on B300.
constexpr int TH = 32;
constexpr int TW = 64;
constexpr int SH = TH + 2 * PC;  // 36
constexpr int SW = TW + 2 * PC;  // 68 floats -> 272B row pitch (16B aligned)
constexpr int NT = 512;          // threads per CTA

__global__ __launch_bounds__(NT, 2)
void kconv_kernel(const float* __restrict__ frames,
                  const float* __restrict__ core,
                  const float* __restrict__ Wt,
                  float* __restrict__ out)
{
    __shared__ float s[SH][SW];

    const int tx = blockIdx.x * TW;          // tile origin x
    const int ty = blockIdx.y * TH;          // tile origin y
    const int bz = blockIdx.z;               // b*N + n

    const size_t plane = (size_t)HC * WC;
    const float* fbase = frames + (size_t)bz * plane;

    // ---- Stage padded frame tile into shared memory (zero halo at borders) ----
    for (int idx = threadIdx.x; idx < SH * SW; idx += NT) {
        const int r = idx / SW;
        const int c = idx - r * SW;
        const int gy = ty + r - PC;
        const int gx = tx + c - PC;
        float v = 0.0f;
        if ((unsigned)gy < (unsigned)HC && (unsigned)gx < (unsigned)WC)
            v = __ldg(&fbase[(size_t)gy * WC + gx]);
        s[r][c] = v;
    }

    // Thread -> output group mapping (one float4 per thread)
    const int g   = threadIdx.x;             // 0..511 (32 rows * 16 groups)
    const int row = g >> 4;                  // 0..31 within tile
    const int xx  = (g & 15) << 2;           // 0..60, multiple of 4
    const int gy  = ty + row;
    const int gx  = tx + xx;
    const size_t pix = (size_t)gy * WC + gx;

    const float* cbase = core + (size_t)bz * (KC * KC) * plane;
    const float* wbase = Wt  + (size_t)bz * plane;
    float*       obase = out + (size_t)bz * plane;

    // Hoist the W load before the barrier: read-once stream, evict-first,
    // and its latency overlaps the smem staging + core loop instead of being
    // exposed at each thread's tail.
    const float4 wv = __ldcs(reinterpret_cast<const float4*>(wbase + pix));

    __syncthreads();

    // Preload the full 5x8 frame window from shared memory FIRST, so the
    // hot loop below is a pure LDG->FMA stream.
    float w[KC][8];
    #pragma unroll
    for (int i = 0; i < KC; ++i) {
        const float* srow = &s[row + i][xx];
        const float4 a  = *reinterpret_cast<const float4*>(srow);
        const float4 bq = *reinterpret_cast<const float4*>(srow + 4);
        w[i][0] = a.x;  w[i][1] = a.y;  w[i][2] = a.z;  w[i][3] = a.w;
        w[i][4] = bq.x; w[i][5] = bq.y; w[i][6] = bq.z; w[i][7] = bq.w;
    }

    float acc0 = 0.f, acc1 = 0.f, acc2 = 0.f, acc3 = 0.f;

    #pragma unroll
    for (int i = 0; i < KC; ++i) {
        #pragma unroll
        for (int j = 0; j < KC; ++j) {
            const int k = i * KC + j;
            // evict-first: core is a 419MB read-once stream
            const float4 cv = __ldcs(
                reinterpret_cast<const float4*>(cbase + (size_t)k * plane + pix));
            acc0 = fmaf(cv.x, w[i][j + 0], acc0);
            acc1 = fmaf(cv.y, w[i][j + 1], acc1);
            acc2 = fmaf(cv.z, w[i][j + 2], acc2);
            acc3 = fmaf(cv.w, w[i][j + 3], acc3);
        }
    }

    float4 o;
    o.x = acc0 * wv.x;
    o.y = acc1 * wv.y;
    o.z = acc2 * wv.z;
    o.w = acc3 * wv.w;
    // streaming store: output is write-once, never re-read
    __stcs(reinterpret_cast<float4*>(obase + pix), o);
}

extern "C" void kernel_launch(void* const* d_in, const int* in_sizes, int n_in,
                              void* d_out, int out_size)
{
    const float* frames = (const float*)d_in[0];
    const float* core   = (const float*)d_in[1];
    const float* Wt     = (const float*)d_in[2];
    float* out          = (float*)d_out;

    dim3 grid(WC / TW, HC / TH, BC * NC);   // (8, 16, 16) = 2048 CTAs
    dim3 block(NT);
    kconv_kernel<<<grid, block>>>(frames, core, Wt, out);
}